// round 2
// baseline (speedup 1.0000x reference)
#include <cuda_runtime.h>
#include <stdint.h>

#define N_NODES 100000
#define N_EDGES 1600000
#define F_IN  64
#define F_HID 64
#define F_OUT 32

// ---------------- static device scratch (no allocation allowed) ----------------
__device__ float g_dinv[N_NODES];
__device__ float g_xws [N_NODES * F_HID];   // (x@W1)*dinv
__device__ float g_h   [N_NODES * F_HID];   // relu hidden
__device__ float g_hws [N_NODES * F_OUT];   // (h@W2)*dinv
__device__ int   g_cnt [N_NODES];           // dst degree counts
__device__ int   g_off [N_NODES + 1];       // CSR offsets
__device__ int   g_cur [N_NODES];           // fill cursors
__device__ int   g_csr [N_EDGES];           // src index per CSR slot
__device__ int   g_is64;

// ---------------- edge index fetch (int64 vs int32 runtime layout) -------------
__device__ __forceinline__ void get_edge(const int* __restrict__ w, int is64,
                                         int e, int& s, int& d) {
    if (is64) {
        s = w[2 * e];
        d = w[2 * N_EDGES + 2 * e];
    } else {
        s = w[e];
        d = w[N_EDGES + e];
    }
}

// detect dtype with one warp: if int64 (values < 100000), odd 32-bit words are 0
__global__ void k_detect(const int* __restrict__ w) {
    int lane = threadIdx.x;
    int nz = (w[2 * lane + 1] != 0) || (w[2 * (lane + 32) + 1] != 0);
    unsigned any = __ballot_sync(0xffffffffu, nz);
    if (lane == 0) g_is64 = (any == 0u);
}

// ---------------- zero counts ----------------
__global__ void k_zero() {
    int i = blockIdx.x * blockDim.x + threadIdx.x;
    if (i < N_NODES) g_cnt[i] = 0;
}

// ---------------- degree histogram ----------------
__global__ void k_hist(const int* __restrict__ ew) {
    int e = blockIdx.x * blockDim.x + threadIdx.x;
    if (e >= N_EDGES) return;
    int s, d;
    get_edge(ew, g_is64, e, s, d);
    atomicAdd(&g_cnt[d], 1);
}

__global__ void k_dinv() {
    int i = blockIdx.x * blockDim.x + threadIdx.x;
    if (i >= N_NODES) return;
    g_dinv[i] = rsqrtf((float)g_cnt[i] + 1.0f);
}

// ---------------- single-block exclusive scan over counts ----------------
__global__ void __launch_bounds__(1024) k_scan() {
    __shared__ int sh[1024];
    const int CH = 98;                 // 1024*98 = 100352 >= N_NODES
    int t = threadIdx.x;
    int base = t * CH;
    int s = 0;
#pragma unroll 7
    for (int i = 0; i < CH; i++) {
        int idx = base + i;
        if (idx < N_NODES) s += g_cnt[idx];
    }
    sh[t] = s;
    __syncthreads();
    for (int ofs = 1; ofs < 1024; ofs <<= 1) {
        int v = (t >= ofs) ? sh[t - ofs] : 0;
        __syncthreads();
        sh[t] += v;
        __syncthreads();
    }
    int run = (t > 0) ? sh[t - 1] : 0;
    for (int i = 0; i < CH; i++) {
        int idx = base + i;
        if (idx < N_NODES) {
            g_off[idx] = run;
            g_cur[idx] = run;
            run += g_cnt[idx];
        }
    }
    if (t == 1023) g_off[N_NODES] = N_EDGES;
}

// ---------------- fill CSR: slot per edge ----------------
__global__ void k_fill(const int* __restrict__ ew) {
    int e = blockIdx.x * blockDim.x + threadIdx.x;
    if (e >= N_EDGES) return;
    int s, d;
    get_edge(ew, g_is64, e, s, d);
    int slot = atomicAdd(&g_cur[d], 1);
    g_csr[slot] = s;
}

// ---------------- GEMM1: xws = (x @ W1) * dinv ----------------
__global__ void __launch_bounds__(256) k_gemm1(const float* __restrict__ x,
                                               const float* __restrict__ W) {
    __shared__ float4 ws[F_IN * (F_HID / 4)];  // 16KB
    int tid = threadIdx.x;
    for (int i = tid; i < F_IN * (F_HID / 4); i += 256)
        ws[i] = ((const float4*)W)[i];
    __syncthreads();

    int row = blockIdx.x * 256 + tid;
    if (row >= N_NODES) return;

    float4 acc[16];
#pragma unroll
    for (int j = 0; j < 16; j++) acc[j] = make_float4(0.f, 0.f, 0.f, 0.f);

    const float4* xr = (const float4*)(x + (size_t)row * F_IN);
#pragma unroll
    for (int kk = 0; kk < 16; kk++) {
        float4 xv = __ldg(xr + kk);
        float xs[4] = {xv.x, xv.y, xv.z, xv.w};
#pragma unroll
        for (int t = 0; t < 4; t++) {
            int k = kk * 4 + t;
            float xk = xs[t];
#pragma unroll
            for (int j = 0; j < 16; j++) {
                float4 w4 = ws[k * 16 + j];
                acc[j].x = fmaf(xk, w4.x, acc[j].x);
                acc[j].y = fmaf(xk, w4.y, acc[j].y);
                acc[j].z = fmaf(xk, w4.z, acc[j].z);
                acc[j].w = fmaf(xk, w4.w, acc[j].w);
            }
        }
    }
    float s = g_dinv[row];
    float4* o = (float4*)(g_xws + (size_t)row * F_HID);
#pragma unroll
    for (int j = 0; j < 16; j++) {
        float4 a = acc[j];
        a.x *= s; a.y *= s; a.z *= s; a.w *= s;
        o[j] = a;
    }
}

// ---------------- aggregate layer 1 + hidden epilogue (warp per node) ----------
// h[i] = relu(dinv[i] * (sum_{e: dst=i} xws[src] + xws[i]) + b1)
__global__ void __launch_bounds__(256) k_agg1(const float* __restrict__ b1) {
    int warp = (blockIdx.x * 256 + threadIdx.x) >> 5;
    int lane = threadIdx.x & 31;
    if (warp >= N_NODES) return;
    int node = warp;

    int off = g_off[node];
    int cnt = g_off[node + 1] - off;

    float2 acc = make_float2(0.f, 0.f);
    for (int k0 = 0; k0 < cnt; k0 += 32) {
        int myidx = (k0 + lane < cnt) ? g_csr[off + k0 + lane] : 0;
        int m = min(32, cnt - k0);
        for (int j = 0; j < m; j++) {
            int s = __shfl_sync(0xffffffffu, myidx, j);
            float2 v = *(const float2*)(g_xws + (size_t)s * F_HID + lane * 2);
            acc.x += v.x;
            acc.y += v.y;
        }
    }
    float2 self = *(const float2*)(g_xws + (size_t)node * F_HID + lane * 2);
    float sc = g_dinv[node];
    float2 b = ((const float2*)b1)[lane];
    float2 r;
    r.x = fmaxf(sc * (acc.x + self.x) + b.x, 0.f);
    r.y = fmaxf(sc * (acc.y + self.y) + b.y, 0.f);
    *(float2*)(g_h + (size_t)node * F_HID + lane * 2) = r;
}

// ---------------- GEMM2: hws = (h @ W2) * dinv ----------------
__global__ void __launch_bounds__(256) k_gemm2(const float* __restrict__ W) {
    __shared__ float4 ws[F_HID * (F_OUT / 4)];  // 8KB
    int tid = threadIdx.x;
    for (int i = tid; i < F_HID * (F_OUT / 4); i += 256)
        ws[i] = ((const float4*)W)[i];
    __syncthreads();

    int row = blockIdx.x * 256 + tid;
    if (row >= N_NODES) return;

    float4 acc[8];
#pragma unroll
    for (int j = 0; j < 8; j++) acc[j] = make_float4(0.f, 0.f, 0.f, 0.f);

    const float4* hr = (const float4*)(g_h + (size_t)row * F_HID);
#pragma unroll
    for (int kk = 0; kk < 16; kk++) {
        float4 hv = __ldg(hr + kk);
        float hs[4] = {hv.x, hv.y, hv.z, hv.w};
#pragma unroll
        for (int t = 0; t < 4; t++) {
            int k = kk * 4 + t;
            float hk = hs[t];
#pragma unroll
            for (int j = 0; j < 8; j++) {
                float4 w4 = ws[k * 8 + j];
                acc[j].x = fmaf(hk, w4.x, acc[j].x);
                acc[j].y = fmaf(hk, w4.y, acc[j].y);
                acc[j].z = fmaf(hk, w4.z, acc[j].z);
                acc[j].w = fmaf(hk, w4.w, acc[j].w);
            }
        }
    }
    float s = g_dinv[row];
    float4* o = (float4*)(g_hws + (size_t)row * F_OUT);
#pragma unroll
    for (int j = 0; j < 8; j++) {
        float4 a = acc[j];
        a.x *= s; a.y *= s; a.z *= s; a.w *= s;
        o[j] = a;
    }
}

// ---------------- aggregate layer 2 + output epilogue (warp per node) ----------
// out[i] = dinv[i] * (sum_{e: dst=i} hws[src] + hws[i]) + b2
__global__ void __launch_bounds__(256) k_agg2(const float* __restrict__ b2,
                                              float* __restrict__ out) {
    int warp = (blockIdx.x * 256 + threadIdx.x) >> 5;
    int lane = threadIdx.x & 31;
    if (warp >= N_NODES) return;
    int node = warp;

    int off = g_off[node];
    int cnt = g_off[node + 1] - off;

    float acc = 0.f;
    for (int k0 = 0; k0 < cnt; k0 += 32) {
        int myidx = (k0 + lane < cnt) ? g_csr[off + k0 + lane] : 0;
        int m = min(32, cnt - k0);
        for (int j = 0; j < m; j++) {
            int s = __shfl_sync(0xffffffffu, myidx, j);
            acc += g_hws[(size_t)s * F_OUT + lane];
        }
    }
    float self = g_hws[(size_t)node * F_OUT + lane];
    float sc = g_dinv[node];
    out[(size_t)node * F_OUT + lane] = sc * (acc + self) + b2[lane];
}

// ---------------- launch ----------------
extern "C" void kernel_launch(void* const* d_in, const int* in_sizes, int n_in,
                              void* d_out, int out_size) {
    const float* x  = (const float*)d_in[0];
    const int*   ew = (const int*)d_in[1];
    const float* W1 = (const float*)d_in[2];
    const float* b1 = (const float*)d_in[3];
    const float* W2 = (const float*)d_in[4];
    const float* b2 = (const float*)d_in[5];
    float* out = (float*)d_out;

    const int T = 256;

    k_detect<<<1, 32>>>(ew);
    k_zero<<<(N_NODES + T - 1) / T, T>>>();
    k_hist<<<(N_EDGES + T - 1) / T, T>>>(ew);
    k_dinv<<<(N_NODES + T - 1) / T, T>>>();
    k_scan<<<1, 1024>>>();
    k_fill<<<(N_EDGES + T - 1) / T, T>>>(ew);

    k_gemm1<<<(N_NODES + T - 1) / T, T>>>(x, W1);
    k_agg1<<<(N_NODES * 32 + T - 1) / T, T>>>(b1);

    k_gemm2<<<(N_NODES + T - 1) / T, T>>>(W2);
    k_agg2<<<(N_NODES * 32 + T - 1) / T, T>>>(b2, out);
}